// round 13
// baseline (speedup 1.0000x reference)
#include <cuda_runtime.h>
#include <cuda_fp16.h>
#include <math.h>
#include <stdint.h>

#define NN 100000
#define NE 1600000
#define ET (NE + NN)
#define LRELU 0.2f

// ---------- scratch ----------
__device__ __half g_h[(size_t)NN * 128];
__device__ __half g_feat[(size_t)NN * 128];
__device__ __half g_x16[(size_t)NN * 128];
__device__ uint32_t g_w0t[128 * 64];   // fp16 [col][kpair]
__device__ uint32_t g_w1t[128 * 64];
__device__ uint32_t g_w2t[64 * 64];
__device__ float g_als[(size_t)NN * 8];
__device__ float g_ald[(size_t)NN * 8];
__device__ __half g_ew[(size_t)ET * 8];
__device__ int   g_rowptr[NN + 1];
__device__ int   g_cnt[NN];
__device__ int   g_srcs[ET];
__device__ int   g_dsts[ET];
__device__ int   g_part[128];

// ---------- forward decls ----------
__global__ void k_gemm8(const __half* __restrict__, const uint32_t* __restrict__,
                        const float* __restrict__, const float* __restrict__,
                        __half* __restrict__, float* __restrict__, float* __restrict__, int);
__global__ void k_gemm1(const __half* __restrict__, const uint32_t* __restrict__,
                        const float* __restrict__, const float* __restrict__,
                        __half* __restrict__, float* __restrict__, float* __restrict__, int);

#define SMEM8 (2 * 128 * 68 * 4)
#define SMEM1 ((128 * 68 + 64 * 68) * 4)

// ---------- side stream ----------
static cudaStream_t g_sB;
static cudaEvent_t g_evFork, g_evJoin;
namespace {
struct StreamInit {
    StreamInit() {
        cudaStreamCreateWithFlags(&g_sB, cudaStreamNonBlocking);
        cudaEventCreateWithFlags(&g_evFork, cudaEventDisableTiming);
        cudaEventCreateWithFlags(&g_evJoin, cudaEventDisableTiming);
        cudaFuncSetAttribute(k_gemm8, cudaFuncAttributeMaxDynamicSharedMemorySize, SMEM8);
        cudaFuncSetAttribute(k_gemm1, cudaFuncAttributeMaxDynamicSharedMemorySize, SMEM1);
    }
};
StreamInit g_streamInit;
}

// ---------------------- prep: fp16 conversions ----------------------
__global__ __launch_bounds__(256) void k_x2h(const float* __restrict__ x, int total8) {
    int i = blockIdx.x * blockDim.x + threadIdx.x;
    if (i >= total8) return;
    float4 f0 = ((const float4*)x)[i * 2];
    float4 f1 = ((const float4*)x)[i * 2 + 1];
    __half2 h0 = __floats2half2_rn(f0.x, f0.y), h1 = __floats2half2_rn(f0.z, f0.w);
    __half2 h2 = __floats2half2_rn(f1.x, f1.y), h3 = __floats2half2_rn(f1.z, f1.w);
    uint4 u = {*(uint32_t*)&h0, *(uint32_t*)&h1, *(uint32_t*)&h2, *(uint32_t*)&h3};
    ((uint4*)g_x16)[i] = u;
}
// all three weight matrices in one launch
__global__ __launch_bounds__(256) void k_wcvt_all(const float* __restrict__ W0,
                                                  const float* __restrict__ W1,
                                                  const float* __restrict__ W2) {
    int i = blockIdx.x * blockDim.x + threadIdx.x;
    if (i < 128 * 64) {
        int col = i >> 6, kp = i & 63;
        __half2 h = __floats2half2_rn(W0[(size_t)(2 * kp) * 128 + col],
                                      W0[(size_t)(2 * kp + 1) * 128 + col]);
        g_w0t[col * 64 + kp] = *(uint32_t*)&h;
    } else if (i < 2 * 128 * 64) {
        int j = i - 128 * 64;
        int col = j >> 6, kp = j & 63;
        __half2 h = __floats2half2_rn(W1[(size_t)(2 * kp) * 128 + col],
                                      W1[(size_t)(2 * kp + 1) * 128 + col]);
        g_w1t[col * 64 + kp] = *(uint32_t*)&h;
    } else if (i < 2 * 128 * 64 + 64 * 64) {
        int j = i - 2 * 128 * 64;
        int col = j >> 6, kp = j & 63;
        __half2 h = __floats2half2_rn(W2[(size_t)(2 * kp) * 64 + col],
                                      W2[(size_t)(2 * kp + 1) * 64 + col]);
        g_w2t[col * 64 + kp] = *(uint32_t*)&h;
    }
}

// ---------------------- CSR build ----------------------
__global__ void k_count(const int* __restrict__ dst, int e) {
    int i = blockIdx.x * blockDim.x + threadIdx.x;
    if (i < e) atomicAdd(&g_cnt[dst[i]], 1);
}
__global__ void k_scan1(int n) {
    __shared__ int sh[1024];
    int tid = threadIdx.x;
    int i = blockIdx.x * 1024 + tid;
    int v = (i < n) ? g_cnt[i] + 1 : 0;   // +1 = self loop (cnt memset to 0)
    sh[tid] = v;
    __syncthreads();
    #pragma unroll
    for (int o = 1; o < 1024; o <<= 1) {
        int t = (tid >= o) ? sh[tid - o] : 0;
        __syncthreads();
        sh[tid] += t;
        __syncthreads();
    }
    if (i < n) g_rowptr[i] = sh[tid] - v;
    if (tid == 1023) g_part[blockIdx.x] = sh[1023];
}
__global__ void k_scan2(int nb) {
    __shared__ int sh[128];
    int tid = threadIdx.x;
    int v = (tid < nb) ? g_part[tid] : 0;
    sh[tid] = v;
    __syncthreads();
    #pragma unroll
    for (int o = 1; o < 128; o <<= 1) {
        int t = (tid >= o) ? sh[tid - o] : 0;
        __syncthreads();
        sh[tid] += t;
        __syncthreads();
    }
    if (tid < nb) sh[tid] = sh[tid] - v;
    __syncthreads();
    if (tid < nb) g_part[tid] = sh[tid];
}
__global__ void k_scan3(int n, int etot) {
    int i = blockIdx.x * 1024 + threadIdx.x;
    if (i < n) {
        int p = g_rowptr[i] + g_part[blockIdx.x];
        g_rowptr[i] = p;
        g_srcs[p] = i;
        g_dsts[p] = i;
        g_cnt[i] = p + 1;
    }
    if (i == 0) g_rowptr[n] = etot;
}
__global__ void k_scatter(const int* __restrict__ src, const int* __restrict__ dst, int e) {
    int i = blockIdx.x * blockDim.x + threadIdx.x;
    if (i < e) {
        int d = dst[i];
        int pos = atomicAdd(&g_cnt[d], 1);
        g_srcs[pos] = src[i];
        g_dsts[pos] = d;
    }
}

// ---------------------- edge weight precompute (8 heads) ----------------------
__global__ __launch_bounds__(256) void k_edgew8(const float* __restrict__ als,
                                                const float* __restrict__ ald,
                                                int etot) {
    int i = blockIdx.x * blockDim.x + threadIdx.x;
    if (i >= etot) return;
    int s = g_srcs[i], d = g_dsts[i];
    float4 a0 = *(const float4*)(als + (size_t)s * 8);
    float4 a1 = *(const float4*)(als + (size_t)s * 8 + 4);
    float4 b0 = *(const float4*)(ald + (size_t)d * 8);
    float4 b1 = *(const float4*)(ald + (size_t)d * 8 + 4);
    float x[8] = {a0.x + b0.x, a0.y + b0.y, a0.z + b0.z, a0.w + b0.w,
                  a1.x + b1.x, a1.y + b1.y, a1.z + b1.z, a1.w + b1.w};
    __half hw[8];
    #pragma unroll
    for (int h = 0; h < 8; h++) {
        float v = (x[h] > 0.f) ? x[h] : LRELU * x[h];
        hw[h] = __float2half_rn(__expf(v));
    }
    *(uint4*)(g_ew + (size_t)i * 8) = *(uint4*)hw;
}

// ---------------------- fp16 mma ----------------------
#define MMA_F16(d, a, b) \
    asm volatile("mma.sync.aligned.m16n8k16.row.col.f32.f16.f16.f32 " \
        "{%0,%1,%2,%3}, {%4,%5,%6,%7}, {%8,%9}, {%0,%1,%2,%3};" \
        : "+f"((d)[0]), "+f"((d)[1]), "+f"((d)[2]), "+f"((d)[3]) \
        : "r"((a)[0]), "r"((a)[1]), "r"((a)[2]), "r"((a)[3]), \
          "r"((b)[0]), "r"((b)[1]))

// ---------------------- GEMM 128x128 + attn coefs (8 heads x 16) ----------------------
__global__ __launch_bounds__(256) void k_gemm8(
    const __half* __restrict__ A, const uint32_t* __restrict__ Wt,
    const float* __restrict__ asr, const float* __restrict__ adr,
    __half* __restrict__ H, float* __restrict__ als, float* __restrict__ ald, int n)
{
    extern __shared__ uint32_t smem[];
    uint32_t* As32 = smem;             // [128][68]
    uint32_t* Bs32 = smem + 128 * 68;  // [128][68]
    int tid = threadIdx.x;
    int wid = tid >> 5, lane = tid & 31;
    int warp_m = wid >> 1, warp_n = wid & 1;
    int g = lane >> 2, c = lane & 3;
    int row0 = blockIdx.x * 128;

    #pragma unroll
    for (int l = 0; l < 8; l++) {
        int idx = tid + l * 256;
        int r = idx >> 4, q = idx & 15;
        int gr = row0 + r;
        uint4 u = make_uint4(0, 0, 0, 0);
        if (gr < n) u = *(const uint4*)(A + (size_t)gr * 128 + q * 8);
        *(uint4*)&As32[r * 68 + q * 4] = u;
    }
    #pragma unroll
    for (int l = 0; l < 8; l++) {
        int idx = tid + l * 256;
        int col = idx >> 4, q = idx & 15;
        *(uint4*)&Bs32[col * 68 + q * 4] = *(const uint4*)(Wt + col * 64 + q * 4);
    }
    __syncthreads();

    float acc[2][8][4];
    #pragma unroll
    for (int mt = 0; mt < 2; mt++)
        #pragma unroll
        for (int nt = 0; nt < 8; nt++)
            #pragma unroll
            for (int j = 0; j < 4; j++) acc[mt][nt][j] = 0.f;

    #pragma unroll
    for (int ks = 0; ks < 8; ks++) {
        int kb = ks * 8;
        uint32_t bf[8][2];
        #pragma unroll
        for (int nt = 0; nt < 8; nt++) {
            int col = warp_n * 64 + nt * 8 + g;
            bf[nt][0] = Bs32[col * 68 + kb + c];
            bf[nt][1] = Bs32[col * 68 + kb + c + 4];
        }
        #pragma unroll
        for (int mt = 0; mt < 2; mt++) {
            int row = warp_m * 32 + mt * 16 + g;
            uint32_t af[4];
            af[0] = As32[row * 68 + kb + c];
            af[1] = As32[(row + 8) * 68 + kb + c];
            af[2] = As32[row * 68 + kb + c + 4];
            af[3] = As32[(row + 8) * 68 + kb + c + 4];
            #pragma unroll
            for (int nt = 0; nt < 8; nt++) MMA_F16(acc[mt][nt], af, bf[nt]);
        }
    }

    #pragma unroll
    for (int mt = 0; mt < 2; mt++) {
        int r_lo = row0 + warp_m * 32 + mt * 16 + g;
        int r_hi = r_lo + 8;
        float sA0[4] = {0, 0, 0, 0}, sA1[4] = {0, 0, 0, 0};
        float sD0[4] = {0, 0, 0, 0}, sD1[4] = {0, 0, 0, 0};
        #pragma unroll
        for (int nt = 0; nt < 8; nt++) {
            int col = warp_n * 64 + nt * 8 + c * 2;
            int hh = nt >> 1;
            float as0 = asr[col], as1 = asr[col + 1];
            float ad0 = adr[col], ad1 = adr[col + 1];
            float* d = acc[mt][nt];
            sA0[hh] = fmaf(d[0], as0, fmaf(d[1], as1, sA0[hh]));
            sA1[hh] = fmaf(d[2], as0, fmaf(d[3], as1, sA1[hh]));
            sD0[hh] = fmaf(d[0], ad0, fmaf(d[1], ad1, sD0[hh]));
            sD1[hh] = fmaf(d[2], ad0, fmaf(d[3], ad1, sD1[hh]));
            if (r_lo < n) *(__half2*)(H + (size_t)r_lo * 128 + col) = __floats2half2_rn(d[0], d[1]);
            if (r_hi < n) *(__half2*)(H + (size_t)r_hi * 128 + col) = __floats2half2_rn(d[2], d[3]);
        }
        #pragma unroll
        for (int hh = 0; hh < 4; hh++) {
            sA0[hh] += __shfl_xor_sync(0xFFFFFFFFu, sA0[hh], 1);
            sA0[hh] += __shfl_xor_sync(0xFFFFFFFFu, sA0[hh], 2);
            sA1[hh] += __shfl_xor_sync(0xFFFFFFFFu, sA1[hh], 1);
            sA1[hh] += __shfl_xor_sync(0xFFFFFFFFu, sA1[hh], 2);
            sD0[hh] += __shfl_xor_sync(0xFFFFFFFFu, sD0[hh], 1);
            sD0[hh] += __shfl_xor_sync(0xFFFFFFFFu, sD0[hh], 2);
            sD1[hh] += __shfl_xor_sync(0xFFFFFFFFu, sD1[hh], 1);
            sD1[hh] += __shfl_xor_sync(0xFFFFFFFFu, sD1[hh], 2);
        }
        if (c == 0) {
            #pragma unroll
            for (int hh = 0; hh < 4; hh++) {
                int hgl = warp_n * 4 + hh;
                if (r_lo < n) { als[(size_t)r_lo * 8 + hgl] = sA0[hh]; ald[(size_t)r_lo * 8 + hgl] = sD0[hh]; }
                if (r_hi < n) { als[(size_t)r_hi * 8 + hgl] = sA1[hh]; ald[(size_t)r_hi * 8 + hgl] = sD1[hh]; }
            }
        }
    }
}

// ---------------------- GEMM 128x64 + attn coefs (1 head x 64) ----------------------
__global__ __launch_bounds__(256) void k_gemm1(
    const __half* __restrict__ A, const uint32_t* __restrict__ Wt,
    const float* __restrict__ asr, const float* __restrict__ adr,
    __half* __restrict__ H, float* __restrict__ als, float* __restrict__ ald, int n)
{
    extern __shared__ uint32_t smem[];
    uint32_t* As32 = smem;
    uint32_t* Bs32 = smem + 128 * 68;
    int tid = threadIdx.x;
    int wid = tid >> 5, lane = tid & 31;
    int g = lane >> 2, c = lane & 3;
    int row0 = blockIdx.x * 128;

    #pragma unroll
    for (int l = 0; l < 8; l++) {
        int idx = tid + l * 256;
        int r = idx >> 4, q = idx & 15;
        int gr = row0 + r;
        uint4 u = make_uint4(0, 0, 0, 0);
        if (gr < n) u = *(const uint4*)(A + (size_t)gr * 128 + q * 8);
        *(uint4*)&As32[r * 68 + q * 4] = u;
    }
    #pragma unroll
    for (int l = 0; l < 4; l++) {
        int idx = tid + l * 256;
        int col = idx >> 4, q = idx & 15;
        *(uint4*)&Bs32[col * 68 + q * 4] = *(const uint4*)(Wt + col * 64 + q * 4);
    }
    __syncthreads();

    float acc[8][4];
    #pragma unroll
    for (int nt = 0; nt < 8; nt++)
        #pragma unroll
        for (int j = 0; j < 4; j++) acc[nt][j] = 0.f;

    #pragma unroll
    for (int ks = 0; ks < 8; ks++) {
        int kb = ks * 8;
        int row = wid * 16 + g;
        uint32_t af[4];
        af[0] = As32[row * 68 + kb + c];
        af[1] = As32[(row + 8) * 68 + kb + c];
        af[2] = As32[row * 68 + kb + c + 4];
        af[3] = As32[(row + 8) * 68 + kb + c + 4];
        #pragma unroll
        for (int nt = 0; nt < 8; nt++) {
            int col = nt * 8 + g;
            uint32_t bf[2];
            bf[0] = Bs32[col * 68 + kb + c];
            bf[1] = Bs32[col * 68 + kb + c + 4];
            MMA_F16(acc[nt], af, bf);
        }
    }

    int r_lo = row0 + wid * 16 + g;
    int r_hi = r_lo + 8;
    float sA0 = 0.f, sA1 = 0.f, sD0 = 0.f, sD1 = 0.f;
    #pragma unroll
    for (int nt = 0; nt < 8; nt++) {
        int col = nt * 8 + c * 2;
        float as0 = asr[col], as1 = asr[col + 1];
        float ad0 = adr[col], ad1 = adr[col + 1];
        float* d = acc[nt];
        sA0 = fmaf(d[0], as0, fmaf(d[1], as1, sA0));
        sA1 = fmaf(d[2], as0, fmaf(d[3], as1, sA1));
        sD0 = fmaf(d[0], ad0, fmaf(d[1], ad1, sD0));
        sD1 = fmaf(d[2], ad0, fmaf(d[3], ad1, sD1));
        if (r_lo < n) *(__half2*)(H + (size_t)r_lo * 64 + col) = __floats2half2_rn(d[0], d[1]);
        if (r_hi < n) *(__half2*)(H + (size_t)r_hi * 64 + col) = __floats2half2_rn(d[2], d[3]);
    }
    sA0 += __shfl_xor_sync(0xFFFFFFFFu, sA0, 1); sA0 += __shfl_xor_sync(0xFFFFFFFFu, sA0, 2);
    sA1 += __shfl_xor_sync(0xFFFFFFFFu, sA1, 1); sA1 += __shfl_xor_sync(0xFFFFFFFFu, sA1, 2);
    sD0 += __shfl_xor_sync(0xFFFFFFFFu, sD0, 1); sD0 += __shfl_xor_sync(0xFFFFFFFFu, sD0, 2);
    sD1 += __shfl_xor_sync(0xFFFFFFFFu, sD1, 1); sD1 += __shfl_xor_sync(0xFFFFFFFFu, sD1, 2);
    if (c == 0) {
        if (r_lo < n) { als[r_lo] = sA0; ald[r_lo] = sD0; }
        if (r_hi < n) { als[r_hi] = sA1; ald[r_hi] = sD1; }
    }
}

// ---------------------- aggregation (8 heads x 16) + fused LN+ReLU ----------------------
__global__ __launch_bounds__(256) void k_agg8(
    const __half* __restrict__ H, const float* __restrict__ bias,
    const float* __restrict__ lng, const float* __restrict__ lnb,
    __half* __restrict__ out, int n)
{
    int w = (blockIdx.x * blockDim.x + threadIdx.x) >> 5;
    if (w >= n) return;
    int lane = threadIdx.x & 31;
    int s = g_rowptr[w], e2 = g_rowptr[w + 1];
    int hd = lane >> 2;
    int d0 = lane * 4;
    float denom = 0.f;
    float ax = 0.f, ay = 0.f, az = 0.f, aw = 0.f;

    int i = s;
    for (; i + 4 <= e2; i += 4) {
        int sv[4];
        float wv[4];
        #pragma unroll
        for (int j = 0; j < 4; j++) sv[j] = g_srcs[i + j];
        #pragma unroll
        for (int j = 0; j < 4; j++) wv[j] = __half2float(g_ew[(size_t)(i + j) * 8 + hd]);
        uint2 raw[4];
        #pragma unroll
        for (int j = 0; j < 4; j++) raw[j] = *(const uint2*)(H + (size_t)sv[j] * 128 + d0);
        #pragma unroll
        for (int j = 0; j < 4; j++) {
            denom += wv[j];
            float2 f01 = __half22float2(*(__half2*)&raw[j].x);
            float2 f23 = __half22float2(*(__half2*)&raw[j].y);
            ax = fmaf(wv[j], f01.x, ax); ay = fmaf(wv[j], f01.y, ay);
            az = fmaf(wv[j], f23.x, az); aw = fmaf(wv[j], f23.y, aw);
        }
    }
    for (; i < e2; ++i) {
        int s0 = g_srcs[i];
        float w0 = __half2float(g_ew[(size_t)i * 8 + hd]);
        denom += w0;
        uint2 raw = *(const uint2*)(H + (size_t)s0 * 128 + d0);
        float2 f01 = __half22float2(*(__half2*)&raw.x);
        float2 f23 = __half22float2(*(__half2*)&raw.y);
        ax = fmaf(w0, f01.x, ax); ay = fmaf(w0, f01.y, ay);
        az = fmaf(w0, f23.x, az); aw = fmaf(w0, f23.y, aw);
    }

    float inv = 1.f / denom;
    float4 bv = *(const float4*)(bias + d0);
    float ox = fmaf(ax, inv, bv.x);
    float oy = fmaf(ay, inv, bv.y);
    float oz = fmaf(az, inv, bv.z);
    float ow = fmaf(aw, inv, bv.w);

    float sm = ox + oy + oz + ow;
    #pragma unroll
    for (int o = 16; o; o >>= 1) sm += __shfl_xor_sync(0xFFFFFFFFu, sm, o);
    float mu = sm * (1.f / 128.f);
    float dx = ox - mu, dy = oy - mu, dz = oz - mu, dw = ow - mu;
    float q = dx * dx + dy * dy + dz * dz + dw * dw;
    #pragma unroll
    for (int o = 16; o; o >>= 1) q += __shfl_xor_sync(0xFFFFFFFFu, q, o);
    float rstd = rsqrtf(q * (1.f / 128.f) + 1e-5f);
    float4 gg = *(const float4*)(lng + d0);
    float4 bb = *(const float4*)(lnb + d0);
    ox = fmaxf(fmaf(dx * rstd, gg.x, bb.x), 0.f);
    oy = fmaxf(fmaf(dy * rstd, gg.y, bb.y), 0.f);
    oz = fmaxf(fmaf(dz * rstd, gg.z, bb.z), 0.f);
    ow = fmaxf(fmaf(dw * rstd, gg.w, bb.w), 0.f);

    __half2 h01 = __floats2half2_rn(ox, oy);
    __half2 h23 = __floats2half2_rn(oz, ow);
    uint2 packed = {*(uint32_t*)&h01, *(uint32_t*)&h23};
    *(uint2*)(out + (size_t)w * 128 + d0) = packed;
}

// ---------------------- aggregation (1 head x 64), in-loop weights + log_softmax ----------------------
__global__ __launch_bounds__(256) void k_agg1_lsm(
    const __half* __restrict__ H, const float* __restrict__ als,
    const float* __restrict__ ald, const float* __restrict__ bias,
    float* __restrict__ out, int n)
{
    int w = (blockIdx.x * blockDim.x + threadIdx.x) >> 5;
    if (w >= n) return;
    int lane = threadIdx.x & 31;
    int s = g_rowptr[w], e2 = g_rowptr[w + 1];
    float aldv = ald[w];
    int d0 = lane * 2;

    float denom = 0.f, acc0 = 0.f, acc1 = 0.f;
    int i = s;
    for (; i + 4 <= e2; i += 4) {
        int sv[4];
        #pragma unroll
        for (int j = 0; j < 4; j++) sv[j] = g_srcs[i + j];
        float wv[4];
        #pragma unroll
        for (int j = 0; j < 4; j++) {
            float x = als[sv[j]] + aldv;
            x = (x > 0.f) ? x : LRELU * x;
            wv[j] = __expf(x);
        }
        __half2 hv[4];
        #pragma unroll
        for (int j = 0; j < 4; j++) hv[j] = *(const __half2*)(H + (size_t)sv[j] * 64 + d0);
        #pragma unroll
        for (int j = 0; j < 4; j++) {
            denom += wv[j];
            float2 f = __half22float2(hv[j]);
            acc0 = fmaf(wv[j], f.x, acc0);
            acc1 = fmaf(wv[j], f.y, acc1);
        }
    }
    for (; i < e2; ++i) {
        int s0 = g_srcs[i];
        float x = als[s0] + aldv;
        x = (x > 0.f) ? x : LRELU * x;
        float w0 = __expf(x);
        denom += w0;
        float2 f = __half22float2(*(const __half2*)(H + (size_t)s0 * 64 + d0));
        acc0 = fmaf(w0, f.x, acc0); acc1 = fmaf(w0, f.y, acc1);
    }
    float inv = 1.f / denom;
    float v0 = fmaf(acc0, inv, bias[d0]);
    float v1 = fmaf(acc1, inv, bias[d0 + 1]);
    float mx = fmaxf(v0, v1);
    #pragma unroll
    for (int o = 16; o; o >>= 1) mx = fmaxf(mx, __shfl_xor_sync(0xFFFFFFFFu, mx, o));
    float se = __expf(v0 - mx) + __expf(v1 - mx);
    #pragma unroll
    for (int o = 16; o; o >>= 1) se += __shfl_xor_sync(0xFFFFFFFFu, se, o);
    float lse = mx + __logf(se);
    out[(size_t)w * 64 + d0] = v0 - lse;
    out[(size_t)w * 64 + d0 + 1] = v1 - lse;
}

// ---------------------- launcher ----------------------
extern "C" void kernel_launch(void* const* d_in, const int* in_sizes, int n_in,
                              void* d_out, int out_size) {
    const float* x   = (const float*)d_in[0];
    const int*   ei  = (const int*)d_in[1];
    const float* W0  = (const float*)d_in[2];
    const float* as0 = (const float*)d_in[3];
    const float* ad0 = (const float*)d_in[4];
    const float* b0  = (const float*)d_in[5];
    const float* W1  = (const float*)d_in[6];
    const float* as1 = (const float*)d_in[7];
    const float* ad1 = (const float*)d_in[8];
    const float* b1  = (const float*)d_in[9];
    const float* W2  = (const float*)d_in[10];
    const float* as2 = (const float*)d_in[11];
    const float* ad2 = (const float*)d_in[12];
    const float* b2  = (const float*)d_in[13];
    const float* ln1g = (const float*)d_in[14];
    const float* ln1b = (const float*)d_in[15];
    const float* ln2g = (const float*)d_in[16];
    const float* ln2b = (const float*)d_in[17];
    float* out = (float*)d_out;

    const int n = in_sizes[0] / 128;
    const int e = in_sizes[1] / 2;
    const int etot = e + n;
    const int* src = ei;
    const int* dst = ei + e;

    __half *h, *feat, *x16;
    float *als, *ald;
    uint32_t *w0t, *w1t, *w2t;
    int* cntp;
    cudaGetSymbolAddress((void**)&h, g_h);
    cudaGetSymbolAddress((void**)&feat, g_feat);
    cudaGetSymbolAddress((void**)&x16, g_x16);
    cudaGetSymbolAddress((void**)&als, g_als);
    cudaGetSymbolAddress((void**)&ald, g_ald);
    cudaGetSymbolAddress((void**)&w0t, g_w0t);
    cudaGetSymbolAddress((void**)&w1t, g_w1t);
    cudaGetSymbolAddress((void**)&w2t, g_w2t);
    cudaGetSymbolAddress((void**)&cntp, g_cnt);

    const int nb_edges256 = (e + 255) / 256;
    const int nb_etot256 = (etot + 255) / 256;
    const int nb_scan = (n + 1023) / 1024;
    const int nb_warp = (n * 32 + 255) / 256;
    const int nb_gemm = (n + 127) / 128;
    const int total8 = n * 128 / 8;
    const int nb_wcvt = (2 * 128 * 64 + 64 * 64 + 255) / 256;

    // default stream: zero counts (memset node), then fork into stream B
    cudaMemsetAsync(cntp, 0, n * sizeof(int), 0);
    cudaEventRecord(g_evFork, 0);
    cudaStreamWaitEvent(g_sB, g_evFork, 0);

    // stream B: fp16 prep + gemm0, overlapped with CSR build
    k_x2h<<<(total8 + 255) / 256, 256, 0, g_sB>>>(x, total8);
    k_wcvt_all<<<nb_wcvt, 256, 0, g_sB>>>(W0, W1, W2);
    k_gemm8<<<nb_gemm, 256, SMEM8, g_sB>>>(x16, w0t, as0, ad0, h, als, ald, n);

    // default stream: CSR build
    k_count<<<nb_edges256, 256>>>(dst, e);
    k_scan1<<<nb_scan, 1024>>>(n);
    k_scan2<<<1, 128>>>(nb_scan);
    k_scan3<<<nb_scan, 1024>>>(n, etot);
    k_scatter<<<nb_edges256, 256>>>(src, dst, e);

    cudaEventRecord(g_evJoin, g_sB);
    cudaStreamWaitEvent(0, g_evJoin, 0);

    k_edgew8<<<nb_etot256, 256>>>(als, ald, etot);
    k_agg8<<<nb_warp, 256>>>(h, b0, ln1g, ln1b, feat, n);

    k_gemm8<<<nb_gemm, 256, SMEM8>>>(feat, w1t, as1, ad1, h, als, ald, n);
    k_edgew8<<<nb_etot256, 256>>>(als, ald, etot);
    k_agg8<<<nb_warp, 256>>>(h, b1, ln2g, ln2b, feat, n);

    k_gemm1<<<nb_gemm, 256, SMEM1>>>(feat, w2t, as2, ad2, h, als, ald, n);
    k_agg1_lsm<<<nb_warp, 256>>>(h, als, ald, b2, out, n);
}

// round 14
// speedup vs baseline: 1.0195x; 1.0195x over previous
#include <cuda_runtime.h>
#include <cuda_fp16.h>
#include <math.h>
#include <stdint.h>

#define NN 100000
#define NE 1600000
#define ET (NE + NN)
#define LRELU 0.2f

// ---------- scratch ----------
__device__ __half g_h[(size_t)NN * 128];
__device__ __half g_feat[(size_t)NN * 128];
__device__ __half g_x16[(size_t)NN * 128];
__device__ uint32_t g_w0t[128 * 64];
__device__ uint32_t g_w1t[128 * 64];
__device__ uint32_t g_w2t[64 * 64];
__device__ float g_als[(size_t)NN * 8];
__device__ float g_ald[(size_t)NN * 8];
__device__ __half g_ew[(size_t)ET * 8];
__device__ int   g_rowptr[NN + 1];
__device__ int   g_cnt[NN];
__device__ int   g_srcs[ET];
__device__ int   g_dsts[ET];
__device__ int   g_part[128];

// ---------- forward decls ----------
__global__ void k_gemm8(const __half* __restrict__, const uint32_t* __restrict__,
                        const float* __restrict__, const float* __restrict__,
                        __half* __restrict__, float* __restrict__, float* __restrict__, int);
__global__ void k_gemm1(const __half* __restrict__, const uint32_t* __restrict__,
                        const float* __restrict__, const float* __restrict__,
                        __half* __restrict__, float* __restrict__, float* __restrict__, int);

#define SMEM8 (2 * 128 * 68 * 4)
#define SMEM1 ((128 * 68 + 64 * 68) * 4)

// ---------- side stream ----------
static cudaStream_t g_sB;
static cudaEvent_t g_evFork, g_evJoin;
namespace {
struct StreamInit {
    StreamInit() {
        cudaStreamCreateWithFlags(&g_sB, cudaStreamNonBlocking);
        cudaEventCreateWithFlags(&g_evFork, cudaEventDisableTiming);
        cudaEventCreateWithFlags(&g_evJoin, cudaEventDisableTiming);
        cudaFuncSetAttribute(k_gemm8, cudaFuncAttributeMaxDynamicSharedMemorySize, SMEM8);
        cudaFuncSetAttribute(k_gemm1, cudaFuncAttributeMaxDynamicSharedMemorySize, SMEM1);
    }
};
StreamInit g_streamInit;
}

// ---------------------- prep: fp16 conversions ----------------------
__global__ __launch_bounds__(256) void k_x2h(const float* __restrict__ x, int total8) {
    int i = blockIdx.x * blockDim.x + threadIdx.x;
    if (i >= total8) return;
    float4 f0 = ((const float4*)x)[i * 2];
    float4 f1 = ((const float4*)x)[i * 2 + 1];
    __half2 h0 = __floats2half2_rn(f0.x, f0.y), h1 = __floats2half2_rn(f0.z, f0.w);
    __half2 h2 = __floats2half2_rn(f1.x, f1.y), h3 = __floats2half2_rn(f1.z, f1.w);
    uint4 u = {*(uint32_t*)&h0, *(uint32_t*)&h1, *(uint32_t*)&h2, *(uint32_t*)&h3};
    ((uint4*)g_x16)[i] = u;
}
__global__ __launch_bounds__(256) void k_wcvt_all(const float* __restrict__ W0,
                                                  const float* __restrict__ W1,
                                                  const float* __restrict__ W2) {
    int i = blockIdx.x * blockDim.x + threadIdx.x;
    if (i < 128 * 64) {
        int col = i >> 6, kp = i & 63;
        __half2 h = __floats2half2_rn(W0[(size_t)(2 * kp) * 128 + col],
                                      W0[(size_t)(2 * kp + 1) * 128 + col]);
        g_w0t[col * 64 + kp] = *(uint32_t*)&h;
    } else if (i < 2 * 128 * 64) {
        int j = i - 128 * 64;
        int col = j >> 6, kp = j & 63;
        __half2 h = __floats2half2_rn(W1[(size_t)(2 * kp) * 128 + col],
                                      W1[(size_t)(2 * kp + 1) * 128 + col]);
        g_w1t[col * 64 + kp] = *(uint32_t*)&h;
    } else if (i < 2 * 128 * 64 + 64 * 64) {
        int j = i - 2 * 128 * 64;
        int col = j >> 6, kp = j & 63;
        __half2 h = __floats2half2_rn(W2[(size_t)(2 * kp) * 64 + col],
                                      W2[(size_t)(2 * kp + 1) * 64 + col]);
        g_w2t[col * 64 + kp] = *(uint32_t*)&h;
    }
}

// ---------------------- CSR build ----------------------
__global__ void k_count(const int* __restrict__ dst, int e) {
    int i = blockIdx.x * blockDim.x + threadIdx.x;
    if (i < e) atomicAdd(&g_cnt[dst[i]], 1);
}
__global__ void k_scan1(int n) {
    __shared__ int sh[1024];
    int tid = threadIdx.x;
    int i = blockIdx.x * 1024 + tid;
    int v = (i < n) ? g_cnt[i] + 1 : 0;   // +1 self loop (cnt was memset 0)
    sh[tid] = v;
    __syncthreads();
    #pragma unroll
    for (int o = 1; o < 1024; o <<= 1) {
        int t = (tid >= o) ? sh[tid - o] : 0;
        __syncthreads();
        sh[tid] += t;
        __syncthreads();
    }
    if (i < n) g_rowptr[i] = sh[tid] - v;    // exclusive within block
    if (tid == 1023) g_part[blockIdx.x] = sh[1023];  // block total
}
// finalize scan (computes own block offset from g_part) + self-loop + cursor
__global__ void k_scan3(int n, int etot) {
    __shared__ int red[32];
    __shared__ int soff;
    int tid = threadIdx.x;
    int acc = 0;
    for (int j = tid; j < blockIdx.x; j += 1024) acc += g_part[j];
    #pragma unroll
    for (int o = 16; o; o >>= 1) acc += __shfl_xor_sync(0xFFFFFFFFu, acc, o);
    if ((tid & 31) == 0) red[tid >> 5] = acc;
    __syncthreads();
    if (tid < 32) {
        int v = red[tid];
        #pragma unroll
        for (int o = 16; o; o >>= 1) v += __shfl_xor_sync(0xFFFFFFFFu, v, o);
        if (tid == 0) soff = v;
    }
    __syncthreads();
    int i = blockIdx.x * 1024 + tid;
    if (i < n) {
        int p = g_rowptr[i] + soff;
        g_rowptr[i] = p;
        g_srcs[p] = i;
        g_dsts[p] = i;
        g_cnt[i] = p + 1;
    }
    if (i == 0) g_rowptr[n] = etot;
}
__global__ void k_scatter(const int* __restrict__ src, const int* __restrict__ dst, int e) {
    int i = blockIdx.x * blockDim.x + threadIdx.x;
    if (i < e) {
        int d = dst[i];
        int pos = atomicAdd(&g_cnt[d], 1);
        g_srcs[pos] = src[i];
        g_dsts[pos] = d;
    }
}

// ---------------------- edge weight precompute ----------------------
__global__ __launch_bounds__(256) void k_edgew8(const float* __restrict__ als,
                                                const float* __restrict__ ald,
                                                int etot) {
    int i = blockIdx.x * blockDim.x + threadIdx.x;
    if (i >= etot) return;
    int s = g_srcs[i], d = g_dsts[i];
    float4 a0 = *(const float4*)(als + (size_t)s * 8);
    float4 a1 = *(const float4*)(als + (size_t)s * 8 + 4);
    float4 b0 = *(const float4*)(ald + (size_t)d * 8);
    float4 b1 = *(const float4*)(ald + (size_t)d * 8 + 4);
    float x[8] = {a0.x + b0.x, a0.y + b0.y, a0.z + b0.z, a0.w + b0.w,
                  a1.x + b1.x, a1.y + b1.y, a1.z + b1.z, a1.w + b1.w};
    __half hw[8];
    #pragma unroll
    for (int h = 0; h < 8; h++) {
        float v = (x[h] > 0.f) ? x[h] : LRELU * x[h];
        hw[h] = __float2half_rn(__expf(v));
    }
    *(uint4*)(g_ew + (size_t)i * 8) = *(uint4*)hw;
}
__global__ __launch_bounds__(256) void k_edgew1(const float* __restrict__ als,
                                                const float* __restrict__ ald,
                                                int etot) {
    int i = blockIdx.x * blockDim.x + threadIdx.x;
    if (i >= etot) return;
    float x = als[g_srcs[i]] + ald[g_dsts[i]];
    x = (x > 0.f) ? x : LRELU * x;
    g_ew[i] = __float2half_rn(__expf(x));
}

// ---------------------- fp16 mma ----------------------
#define MMA_F16(d, a, b) \
    asm volatile("mma.sync.aligned.m16n8k16.row.col.f32.f16.f16.f32 " \
        "{%0,%1,%2,%3}, {%4,%5,%6,%7}, {%8,%9}, {%0,%1,%2,%3};" \
        : "+f"((d)[0]), "+f"((d)[1]), "+f"((d)[2]), "+f"((d)[3]) \
        : "r"((a)[0]), "r"((a)[1]), "r"((a)[2]), "r"((a)[3]), \
          "r"((b)[0]), "r"((b)[1]))

// ---------------------- GEMM 128x128 + attn coefs (8 heads x 16) ----------------------
__global__ __launch_bounds__(256) void k_gemm8(
    const __half* __restrict__ A, const uint32_t* __restrict__ Wt,
    const float* __restrict__ asr, const float* __restrict__ adr,
    __half* __restrict__ H, float* __restrict__ als, float* __restrict__ ald, int n)
{
    extern __shared__ uint32_t smem[];
    uint32_t* As32 = smem;
    uint32_t* Bs32 = smem + 128 * 68;
    int tid = threadIdx.x;
    int wid = tid >> 5, lane = tid & 31;
    int warp_m = wid >> 1, warp_n = wid & 1;
    int g = lane >> 2, c = lane & 3;
    int row0 = blockIdx.x * 128;

    #pragma unroll
    for (int l = 0; l < 8; l++) {
        int idx = tid + l * 256;
        int r = idx >> 4, q = idx & 15;
        int gr = row0 + r;
        uint4 u = make_uint4(0, 0, 0, 0);
        if (gr < n) u = *(const uint4*)(A + (size_t)gr * 128 + q * 8);
        *(uint4*)&As32[r * 68 + q * 4] = u;
    }
    #pragma unroll
    for (int l = 0; l < 8; l++) {
        int idx = tid + l * 256;
        int col = idx >> 4, q = idx & 15;
        *(uint4*)&Bs32[col * 68 + q * 4] = *(const uint4*)(Wt + col * 64 + q * 4);
    }
    __syncthreads();

    float acc[2][8][4];
    #pragma unroll
    for (int mt = 0; mt < 2; mt++)
        #pragma unroll
        for (int nt = 0; nt < 8; nt++)
            #pragma unroll
            for (int j = 0; j < 4; j++) acc[mt][nt][j] = 0.f;

    #pragma unroll
    for (int ks = 0; ks < 8; ks++) {
        int kb = ks * 8;
        uint32_t bf[8][2];
        #pragma unroll
        for (int nt = 0; nt < 8; nt++) {
            int col = warp_n * 64 + nt * 8 + g;
            bf[nt][0] = Bs32[col * 68 + kb + c];
            bf[nt][1] = Bs32[col * 68 + kb + c + 4];
        }
        #pragma unroll
        for (int mt = 0; mt < 2; mt++) {
            int row = warp_m * 32 + mt * 16 + g;
            uint32_t af[4];
            af[0] = As32[row * 68 + kb + c];
            af[1] = As32[(row + 8) * 68 + kb + c];
            af[2] = As32[row * 68 + kb + c + 4];
            af[3] = As32[(row + 8) * 68 + kb + c + 4];
            #pragma unroll
            for (int nt = 0; nt < 8; nt++) MMA_F16(acc[mt][nt], af, bf[nt]);
        }
    }

    #pragma unroll
    for (int mt = 0; mt < 2; mt++) {
        int r_lo = row0 + warp_m * 32 + mt * 16 + g;
        int r_hi = r_lo + 8;
        float sA0[4] = {0, 0, 0, 0}, sA1[4] = {0, 0, 0, 0};
        float sD0[4] = {0, 0, 0, 0}, sD1[4] = {0, 0, 0, 0};
        #pragma unroll
        for (int nt = 0; nt < 8; nt++) {
            int col = warp_n * 64 + nt * 8 + c * 2;
            int hh = nt >> 1;
            float as0 = asr[col], as1 = asr[col + 1];
            float ad0 = adr[col], ad1 = adr[col + 1];
            float* d = acc[mt][nt];
            sA0[hh] = fmaf(d[0], as0, fmaf(d[1], as1, sA0[hh]));
            sA1[hh] = fmaf(d[2], as0, fmaf(d[3], as1, sA1[hh]));
            sD0[hh] = fmaf(d[0], ad0, fmaf(d[1], ad1, sD0[hh]));
            sD1[hh] = fmaf(d[2], ad0, fmaf(d[3], ad1, sD1[hh]));
            if (r_lo < n) *(__half2*)(H + (size_t)r_lo * 128 + col) = __floats2half2_rn(d[0], d[1]);
            if (r_hi < n) *(__half2*)(H + (size_t)r_hi * 128 + col) = __floats2half2_rn(d[2], d[3]);
        }
        #pragma unroll
        for (int hh = 0; hh < 4; hh++) {
            sA0[hh] += __shfl_xor_sync(0xFFFFFFFFu, sA0[hh], 1);
            sA0[hh] += __shfl_xor_sync(0xFFFFFFFFu, sA0[hh], 2);
            sA1[hh] += __shfl_xor_sync(0xFFFFFFFFu, sA1[hh], 1);
            sA1[hh] += __shfl_xor_sync(0xFFFFFFFFu, sA1[hh], 2);
            sD0[hh] += __shfl_xor_sync(0xFFFFFFFFu, sD0[hh], 1);
            sD0[hh] += __shfl_xor_sync(0xFFFFFFFFu, sD0[hh], 2);
            sD1[hh] += __shfl_xor_sync(0xFFFFFFFFu, sD1[hh], 1);
            sD1[hh] += __shfl_xor_sync(0xFFFFFFFFu, sD1[hh], 2);
        }
        if (c == 0) {
            #pragma unroll
            for (int hh = 0; hh < 4; hh++) {
                int hgl = warp_n * 4 + hh;
                if (r_lo < n) { als[(size_t)r_lo * 8 + hgl] = sA0[hh]; ald[(size_t)r_lo * 8 + hgl] = sD0[hh]; }
                if (r_hi < n) { als[(size_t)r_hi * 8 + hgl] = sA1[hh]; ald[(size_t)r_hi * 8 + hgl] = sD1[hh]; }
            }
        }
    }
}

// ---------------------- GEMM 128x64 + attn coefs (1 head x 64) ----------------------
__global__ __launch_bounds__(256) void k_gemm1(
    const __half* __restrict__ A, const uint32_t* __restrict__ Wt,
    const float* __restrict__ asr, const float* __restrict__ adr,
    __half* __restrict__ H, float* __restrict__ als, float* __restrict__ ald, int n)
{
    extern __shared__ uint32_t smem[];
    uint32_t* As32 = smem;
    uint32_t* Bs32 = smem + 128 * 68;
    int tid = threadIdx.x;
    int wid = tid >> 5, lane = tid & 31;
    int g = lane >> 2, c = lane & 3;
    int row0 = blockIdx.x * 128;

    #pragma unroll
    for (int l = 0; l < 8; l++) {
        int idx = tid + l * 256;
        int r = idx >> 4, q = idx & 15;
        int gr = row0 + r;
        uint4 u = make_uint4(0, 0, 0, 0);
        if (gr < n) u = *(const uint4*)(A + (size_t)gr * 128 + q * 8);
        *(uint4*)&As32[r * 68 + q * 4] = u;
    }
    #pragma unroll
    for (int l = 0; l < 4; l++) {
        int idx = tid + l * 256;
        int col = idx >> 4, q = idx & 15;
        *(uint4*)&Bs32[col * 68 + q * 4] = *(const uint4*)(Wt + col * 64 + q * 4);
    }
    __syncthreads();

    float acc[8][4];
    #pragma unroll
    for (int nt = 0; nt < 8; nt++)
        #pragma unroll
        for (int j = 0; j < 4; j++) acc[nt][j] = 0.f;

    #pragma unroll
    for (int ks = 0; ks < 8; ks++) {
        int kb = ks * 8;
        int row = wid * 16 + g;
        uint32_t af[4];
        af[0] = As32[row * 68 + kb + c];
        af[1] = As32[(row + 8) * 68 + kb + c];
        af[2] = As32[row * 68 + kb + c + 4];
        af[3] = As32[(row + 8) * 68 + kb + c + 4];
        #pragma unroll
        for (int nt = 0; nt < 8; nt++) {
            int col = nt * 8 + g;
            uint32_t bf[2];
            bf[0] = Bs32[col * 68 + kb + c];
            bf[1] = Bs32[col * 68 + kb + c + 4];
            MMA_F16(acc[nt], af, bf);
        }
    }

    int r_lo = row0 + wid * 16 + g;
    int r_hi = r_lo + 8;
    float sA0 = 0.f, sA1 = 0.f, sD0 = 0.f, sD1 = 0.f;
    #pragma unroll
    for (int nt = 0; nt < 8; nt++) {
        int col = nt * 8 + c * 2;
        float as0 = asr[col], as1 = asr[col + 1];
        float ad0 = adr[col], ad1 = adr[col + 1];
        float* d = acc[nt];
        sA0 = fmaf(d[0], as0, fmaf(d[1], as1, sA0));
        sA1 = fmaf(d[2], as0, fmaf(d[3], as1, sA1));
        sD0 = fmaf(d[0], ad0, fmaf(d[1], ad1, sD0));
        sD1 = fmaf(d[2], ad0, fmaf(d[3], ad1, sD1));
        if (r_lo < n) *(__half2*)(H + (size_t)r_lo * 64 + col) = __floats2half2_rn(d[0], d[1]);
        if (r_hi < n) *(__half2*)(H + (size_t)r_hi * 64 + col) = __floats2half2_rn(d[2], d[3]);
    }
    sA0 += __shfl_xor_sync(0xFFFFFFFFu, sA0, 1); sA0 += __shfl_xor_sync(0xFFFFFFFFu, sA0, 2);
    sA1 += __shfl_xor_sync(0xFFFFFFFFu, sA1, 1); sA1 += __shfl_xor_sync(0xFFFFFFFFu, sA1, 2);
    sD0 += __shfl_xor_sync(0xFFFFFFFFu, sD0, 1); sD0 += __shfl_xor_sync(0xFFFFFFFFu, sD0, 2);
    sD1 += __shfl_xor_sync(0xFFFFFFFFu, sD1, 1); sD1 += __shfl_xor_sync(0xFFFFFFFFu, sD1, 2);
    if (c == 0) {
        if (r_lo < n) { als[r_lo] = sA0; ald[r_lo] = sD0; }
        if (r_hi < n) { als[r_hi] = sA1; ald[r_hi] = sD1; }
    }
}

// ---------------------- aggregation (8 heads x 16) + fused LN+ReLU ----------------------
__global__ __launch_bounds__(256) void k_agg8(
    const __half* __restrict__ H, const float* __restrict__ bias,
    const float* __restrict__ lng, const float* __restrict__ lnb,
    __half* __restrict__ out, int n)
{
    int w = (blockIdx.x * blockDim.x + threadIdx.x) >> 5;
    if (w >= n) return;
    int lane = threadIdx.x & 31;
    int s = g_rowptr[w], e2 = g_rowptr[w + 1];
    int hd = lane >> 2;
    int d0 = lane * 4;
    float denom = 0.f;
    float ax = 0.f, ay = 0.f, az = 0.f, aw = 0.f;

    int i = s;
    for (; i + 4 <= e2; i += 4) {
        int sv[4];
        float wv[4];
        #pragma unroll
        for (int j = 0; j < 4; j++) sv[j] = g_srcs[i + j];
        #pragma unroll
        for (int j = 0; j < 4; j++) wv[j] = __half2float(g_ew[(size_t)(i + j) * 8 + hd]);
        uint2 raw[4];
        #pragma unroll
        for (int j = 0; j < 4; j++) raw[j] = *(const uint2*)(H + (size_t)sv[j] * 128 + d0);
        #pragma unroll
        for (int j = 0; j < 4; j++) {
            denom += wv[j];
            float2 f01 = __half22float2(*(__half2*)&raw[j].x);
            float2 f23 = __half22float2(*(__half2*)&raw[j].y);
            ax = fmaf(wv[j], f01.x, ax); ay = fmaf(wv[j], f01.y, ay);
            az = fmaf(wv[j], f23.x, az); aw = fmaf(wv[j], f23.y, aw);
        }
    }
    for (; i < e2; ++i) {
        int s0 = g_srcs[i];
        float w0 = __half2float(g_ew[(size_t)i * 8 + hd]);
        denom += w0;
        uint2 raw = *(const uint2*)(H + (size_t)s0 * 128 + d0);
        float2 f01 = __half22float2(*(__half2*)&raw.x);
        float2 f23 = __half22float2(*(__half2*)&raw.y);
        ax = fmaf(w0, f01.x, ax); ay = fmaf(w0, f01.y, ay);
        az = fmaf(w0, f23.x, az); aw = fmaf(w0, f23.y, aw);
    }

    float inv = 1.f / denom;
    float4 bv = *(const float4*)(bias + d0);
    float ox = fmaf(ax, inv, bv.x);
    float oy = fmaf(ay, inv, bv.y);
    float oz = fmaf(az, inv, bv.z);
    float ow = fmaf(aw, inv, bv.w);

    float sm = ox + oy + oz + ow;
    #pragma unroll
    for (int o = 16; o; o >>= 1) sm += __shfl_xor_sync(0xFFFFFFFFu, sm, o);
    float mu = sm * (1.f / 128.f);
    float dx = ox - mu, dy = oy - mu, dz = oz - mu, dw = ow - mu;
    float q = dx * dx + dy * dy + dz * dz + dw * dw;
    #pragma unroll
    for (int o = 16; o; o >>= 1) q += __shfl_xor_sync(0xFFFFFFFFu, q, o);
    float rstd = rsqrtf(q * (1.f / 128.f) + 1e-5f);
    float4 gg = *(const float4*)(lng + d0);
    float4 bb = *(const float4*)(lnb + d0);
    ox = fmaxf(fmaf(dx * rstd, gg.x, bb.x), 0.f);
    oy = fmaxf(fmaf(dy * rstd, gg.y, bb.y), 0.f);
    oz = fmaxf(fmaf(dz * rstd, gg.z, bb.z), 0.f);
    ow = fmaxf(fmaf(dw * rstd, gg.w, bb.w), 0.f);

    __half2 h01 = __floats2half2_rn(ox, oy);
    __half2 h23 = __floats2half2_rn(oz, ow);
    uint2 packed = {*(uint32_t*)&h01, *(uint32_t*)&h23};
    *(uint2*)(out + (size_t)w * 128 + d0) = packed;
}

// ---------------------- aggregation (1 head x 64) + log_softmax ----------------------
__global__ __launch_bounds__(256) void k_agg1_lsm(
    const __half* __restrict__ H, const float* __restrict__ bias,
    float* __restrict__ out, int n)
{
    int w = (blockIdx.x * blockDim.x + threadIdx.x) >> 5;
    if (w >= n) return;
    int lane = threadIdx.x & 31;
    int s = g_rowptr[w], e2 = g_rowptr[w + 1];
    int d0 = lane * 2;

    float denom = 0.f, acc0 = 0.f, acc1 = 0.f;
    int i = s;
    for (; i + 4 <= e2; i += 4) {
        int sv[4];
        float wv[4];
        #pragma unroll
        for (int j = 0; j < 4; j++) sv[j] = g_srcs[i + j];
        #pragma unroll
        for (int j = 0; j < 4; j++) wv[j] = __half2float(g_ew[i + j]);
        __half2 hv[4];
        #pragma unroll
        for (int j = 0; j < 4; j++) hv[j] = *(const __half2*)(H + (size_t)sv[j] * 64 + d0);
        #pragma unroll
        for (int j = 0; j < 4; j++) {
            denom += wv[j];
            float2 f = __half22float2(hv[j]);
            acc0 = fmaf(wv[j], f.x, acc0);
            acc1 = fmaf(wv[j], f.y, acc1);
        }
    }
    for (; i < e2; ++i) {
        int s0 = g_srcs[i];
        float w0 = __half2float(g_ew[i]);
        denom += w0;
        float2 f = __half22float2(*(const __half2*)(H + (size_t)s0 * 64 + d0));
        acc0 = fmaf(w0, f.x, acc0); acc1 = fmaf(w0, f.y, acc1);
    }
    float inv = 1.f / denom;
    float v0 = fmaf(acc0, inv, bias[d0]);
    float v1 = fmaf(acc1, inv, bias[d0 + 1]);
    float mx = fmaxf(v0, v1);
    #pragma unroll
    for (int o = 16; o; o >>= 1) mx = fmaxf(mx, __shfl_xor_sync(0xFFFFFFFFu, mx, o));
    float se = __expf(v0 - mx) + __expf(v1 - mx);
    #pragma unroll
    for (int o = 16; o; o >>= 1) se += __shfl_xor_sync(0xFFFFFFFFu, se, o);
    float lse = mx + __logf(se);
    out[(size_t)w * 64 + d0] = v0 - lse;
    out[(size_t)w * 64 + d0 + 1] = v1 - lse;
}

// ---------------------- launcher ----------------------
extern "C" void kernel_launch(void* const* d_in, const int* in_sizes, int n_in,
                              void* d_out, int out_size) {
    const float* x   = (const float*)d_in[0];
    const int*   ei  = (const int*)d_in[1];
    const float* W0  = (const float*)d_in[2];
    const float* as0 = (const float*)d_in[3];
    const float* ad0 = (const float*)d_in[4];
    const float* b0  = (const float*)d_in[5];
    const float* W1  = (const float*)d_in[6];
    const float* as1 = (const float*)d_in[7];
    const float* ad1 = (const float*)d_in[8];
    const float* b1  = (const float*)d_in[9];
    const float* W2  = (const float*)d_in[10];
    const float* as2 = (const float*)d_in[11];
    const float* ad2 = (const float*)d_in[12];
    const float* b2  = (const float*)d_in[13];
    const float* ln1g = (const float*)d_in[14];
    const float* ln1b = (const float*)d_in[15];
    const float* ln2g = (const float*)d_in[16];
    const float* ln2b = (const float*)d_in[17];
    float* out = (float*)d_out;

    const int n = in_sizes[0] / 128;
    const int e = in_sizes[1] / 2;
    const int etot = e + n;
    const int* src = ei;
    const int* dst = ei + e;

    __half *h, *feat, *x16;
    float *als, *ald;
    uint32_t *w0t, *w1t, *w2t;
    int* cntp;
    cudaGetSymbolAddress((void**)&h, g_h);
    cudaGetSymbolAddress((void**)&feat, g_feat);
    cudaGetSymbolAddress((void**)&x16, g_x16);
    cudaGetSymbolAddress((void**)&als, g_als);
    cudaGetSymbolAddress((void**)&ald, g_ald);
    cudaGetSymbolAddress((void**)&w0t, g_w0t);
    cudaGetSymbolAddress((void**)&w1t, g_w1t);
    cudaGetSymbolAddress((void**)&w2t, g_w2t);
    cudaGetSymbolAddress((void**)&cntp, g_cnt);

    const int nb_edges256 = (e + 255) / 256;
    const int nb_etot256 = (etot + 255) / 256;
    const int nb_scan = (n + 1023) / 1024;
    const int nb_warp = (n * 32 + 255) / 256;
    const int nb_gemm = (n + 127) / 128;
    const int total8 = n * 128 / 8;
    const int nb_wcvt = (2 * 128 * 64 + 64 * 64 + 255) / 256;

    // default stream: zero counts, then fork into stream B
    cudaMemsetAsync(cntp, 0, n * sizeof(int), 0);
    cudaEventRecord(g_evFork, 0);
    cudaStreamWaitEvent(g_sB, g_evFork, 0);

    // stream B: fp16 prep + gemm0, overlapped with CSR build
    k_x2h<<<(total8 + 255) / 256, 256, 0, g_sB>>>(x, total8);
    k_wcvt_all<<<nb_wcvt, 256, 0, g_sB>>>(W0, W1, W2);
    k_gemm8<<<nb_gemm, 256, SMEM8, g_sB>>>(x16, w0t, as0, ad0, h, als, ald, n);

    // default stream: CSR build (scan2 merged into scan3)
    k_count<<<nb_edges256, 256>>>(dst, e);
    k_scan1<<<nb_scan, 1024>>>(n);
    k_scan3<<<nb_scan, 1024>>>(n, etot);
    k_scatter<<<nb_edges256, 256>>>(src, dst, e);

    cudaEventRecord(g_evJoin, g_sB);
    cudaStreamWaitEvent(0, g_evJoin, 0);

    k_edgew8<<<nb_etot256, 256>>>(als, ald, etot);
    k_agg8<<<nb_warp, 256>>>(h, b0, ln1g, ln1b, feat, n);

    k_gemm8<<<nb_gemm, 256, SMEM8>>>(feat, w1t, as1, ad1, h, als, ald, n);
    k_edgew8<<<nb_etot256, 256>>>(als, ald, etot);
    k_agg8<<<nb_warp, 256>>>(h, b1, ln2g, ln2b, feat, n);

    k_gemm1<<<nb_gemm, 256, SMEM1>>>(feat, w2t, as2, ad2, h, als, ald, n);
    k_edgew1<<<nb_etot256, 256>>>(als, ald, etot);
    k_agg1_lsm<<<nb_warp, 256>>>(h, b2, out, n);
}